// round 1
// baseline (speedup 1.0000x reference)
#include <cuda_runtime.h>
#include <cuda_bf16.h>
#include <math.h>

#define HIDDEN 3072
#define SEQ 2048
#define NH 24
#define HD 128
#define MLPD 12288
#define W1N 21504   // 3*HIDDEN + MLPD
#define CATN 15360  // HIDDEN + MLPD
#define MODN 9216   // 3*HIDDEN

// ---------------- scratch (device globals; no allocations allowed) ----------
__device__ float d_mod[MODN];
__device__ float d_xmod[(size_t)SEQ * HIDDEN];
__device__ float d_h[(size_t)SEQ * W1N];
__device__ float d_q[(size_t)NH * SEQ * HD];
__device__ float d_k[(size_t)NH * SEQ * HD];
__device__ float d_v[(size_t)NH * SEQ * HD];
__device__ float d_s[(size_t)NH * SEQ * SEQ];
__device__ float d_cat[(size_t)SEQ * CATN];

// ---------------- mod = silu(vec) @ mod_w + mod_b ---------------------------
__global__ void mod_gemv_kernel(const float* __restrict__ vec,
                                const float* __restrict__ mod_w,
                                const float* __restrict__ mod_b,
                                float* __restrict__ mod) {
    __shared__ float sv[HIDDEN];
    for (int i = threadIdx.x; i < HIDDEN; i += 256) {
        float v = vec[i];
        sv[i] = v / (1.0f + expf(-v));
    }
    __syncthreads();
    int j = blockIdx.x * 256 + threadIdx.x;
    const float* wp = mod_w + j;
    float acc = 0.0f;
#pragma unroll 8
    for (int k = 0; k < HIDDEN; k++) acc = fmaf(sv[k], wp[(size_t)k * MODN], acc);
    mod[j] = acc + mod_b[j];
}

// ---------------- x_mod = (1+scale)*LN(x) + shift ---------------------------
__global__ void ln_mod_kernel(const float* __restrict__ x) {
    int row = blockIdx.x;
    const float* xr = x + (size_t)row * HIDDEN;
    __shared__ float r1[256], r2[256];
    float s = 0.0f, s2 = 0.0f;
    for (int i = threadIdx.x; i < HIDDEN; i += 256) {
        float v = xr[i];
        s += v;
        s2 = fmaf(v, v, s2);
    }
    r1[threadIdx.x] = s; r2[threadIdx.x] = s2;
    __syncthreads();
    for (int o = 128; o > 0; o >>= 1) {
        if (threadIdx.x < o) { r1[threadIdx.x] += r1[threadIdx.x + o]; r2[threadIdx.x] += r2[threadIdx.x + o]; }
        __syncthreads();
    }
    float mu  = r1[0] * (1.0f / HIDDEN);
    float var = r2[0] * (1.0f / HIDDEN) - mu * mu;
    float inv = rsqrtf(var + 1e-6f);
    float* orow = d_xmod + (size_t)row * HIDDEN;
    for (int i = threadIdx.x; i < HIDDEN; i += 256) {
        float sc = 1.0f + d_mod[HIDDEN + i];
        orow[i] = (xr[i] - mu) * inv * sc + d_mod[i];
    }
}

// ---------------- generic tiled SGEMM (128x128x16, 8x8 microtile) -----------
// C = alpha * (A @ op(B)) [+ bias] [gated-residual], batched via blockIdx.z.
// mode 0: C = alpha*acc
// mode 1: C = acc + bias[n]
// mode 2: C = resid[m,n] + gate[n]*(acc + bias[n])
#define BM 128
#define BN 128
#define BK 16
__global__ __launch_bounds__(256) void sgemm_kernel(
    const float* __restrict__ A, int lda, long long sA,
    const float* __restrict__ B, int ldb, long long sB, int transB,
    float* __restrict__ C, int ldc, long long sC,
    int K, float alpha, int mode,
    const float* __restrict__ bias,
    const float* __restrict__ resid,
    const float* __restrict__ gate) {
    __shared__ float As[BK][BM + 4];
    __shared__ float Bs[BK][BN + 4];
    long long bz = blockIdx.z;
    A += bz * sA; B += bz * sB; C += bz * sC;
    const int m0 = blockIdx.y * BM, n0 = blockIdx.x * BN;
    const int tid = threadIdx.x;
    const int tx = tid & 15, ty = tid >> 4;
    float acc[8][8];
#pragma unroll
    for (int i = 0; i < 8; i++)
#pragma unroll
        for (int j = 0; j < 8; j++) acc[i][j] = 0.0f;

    for (int k0 = 0; k0 < K; k0 += BK) {
#pragma unroll
        for (int t = 0; t < 2; t++) {
            int f = tid + t * 256;
            int r = f >> 2, c4 = (f & 3) << 2;
            float4 v = *reinterpret_cast<const float4*>(A + (long long)(m0 + r) * lda + k0 + c4);
            As[c4 + 0][r] = v.x; As[c4 + 1][r] = v.y; As[c4 + 2][r] = v.z; As[c4 + 3][r] = v.w;
        }
        if (transB) {
#pragma unroll
            for (int t = 0; t < 2; t++) {
                int f = tid + t * 256;
                int r = f >> 2, c4 = (f & 3) << 2;
                float4 v = *reinterpret_cast<const float4*>(B + (long long)(n0 + r) * ldb + k0 + c4);
                Bs[c4 + 0][r] = v.x; Bs[c4 + 1][r] = v.y; Bs[c4 + 2][r] = v.z; Bs[c4 + 3][r] = v.w;
            }
        } else {
#pragma unroll
            for (int t = 0; t < 2; t++) {
                int f = tid + t * 256;
                int kr = f >> 5, c4 = (f & 31) << 2;
                float4 v = *reinterpret_cast<const float4*>(B + (long long)(k0 + kr) * ldb + n0 + c4);
                *reinterpret_cast<float4*>(&Bs[kr][c4]) = v;
            }
        }
        __syncthreads();
#pragma unroll
        for (int kk = 0; kk < BK; kk++) {
            float a[8], b[8];
            *reinterpret_cast<float4*>(a)     = *reinterpret_cast<const float4*>(&As[kk][ty * 4]);
            *reinterpret_cast<float4*>(a + 4) = *reinterpret_cast<const float4*>(&As[kk][64 + ty * 4]);
            *reinterpret_cast<float4*>(b)     = *reinterpret_cast<const float4*>(&Bs[kk][tx * 4]);
            *reinterpret_cast<float4*>(b + 4) = *reinterpret_cast<const float4*>(&Bs[kk][64 + tx * 4]);
#pragma unroll
            for (int i = 0; i < 8; i++)
#pragma unroll
                for (int j = 0; j < 8; j++) acc[i][j] = fmaf(a[i], b[j], acc[i][j]);
        }
        __syncthreads();
    }
#pragma unroll
    for (int i = 0; i < 8; i++) {
        int m = m0 + ((i < 4) ? (ty * 4 + i) : (64 + ty * 4 + i - 4));
#pragma unroll
        for (int jg = 0; jg < 2; jg++) {
            int n = n0 + jg * 64 + tx * 4;
            float4 r;
            r.x = acc[i][jg * 4 + 0]; r.y = acc[i][jg * 4 + 1];
            r.z = acc[i][jg * 4 + 2]; r.w = acc[i][jg * 4 + 3];
            if (mode == 0) {
                r.x *= alpha; r.y *= alpha; r.z *= alpha; r.w *= alpha;
            } else {
                float4 bv = *reinterpret_cast<const float4*>(bias + n);
                r.x += bv.x; r.y += bv.y; r.z += bv.z; r.w += bv.w;
                if (mode == 2) {
                    float4 gv = *reinterpret_cast<const float4*>(gate + n);
                    float4 xv = *reinterpret_cast<const float4*>(resid + (long long)m * ldc + n);
                    r.x = fmaf(gv.x, r.x, xv.x);
                    r.y = fmaf(gv.y, r.y, xv.y);
                    r.z = fmaf(gv.z, r.z, xv.z);
                    r.w = fmaf(gv.w, r.w, xv.w);
                }
            }
            *reinterpret_cast<float4*>(C + (long long)m * ldc + n) = r;
        }
    }
}

// ---------------- split qkv, RMSNorm q/k, RoPE, transpose to [h][l][d] ------
__global__ void qkv_prep_kernel(const float* __restrict__ pe,
                                const float* __restrict__ qnw,
                                const float* __restrict__ knw) {
    int wg = blockIdx.x * 8 + (threadIdx.x >> 5);
    int lane = threadIdx.x & 31;
    int l = wg / NH, hd = wg % NH;
    const float* base = d_h + (size_t)l * W1N + hd * HD + lane * 4;
    float4 qv = *reinterpret_cast<const float4*>(base);
    float4 kv = *reinterpret_cast<const float4*>(base + HIDDEN);
    float4 vv = *reinterpret_cast<const float4*>(base + 2 * HIDDEN);

    float sq = qv.x * qv.x + qv.y * qv.y + qv.z * qv.z + qv.w * qv.w;
    float sk = kv.x * kv.x + kv.y * kv.y + kv.z * kv.z + kv.w * kv.w;
#pragma unroll
    for (int o = 16; o > 0; o >>= 1) {
        sq += __shfl_xor_sync(0xffffffffu, sq, o);
        sk += __shfl_xor_sync(0xffffffffu, sk, o);
    }
    float rq = rsqrtf(sq * (1.0f / HD) + 1e-6f);
    float rk = rsqrtf(sk * (1.0f / HD) + 1e-6f);
    float4 wq = *reinterpret_cast<const float4*>(qnw + lane * 4);
    float4 wk = *reinterpret_cast<const float4*>(knw + lane * 4);
    float q0 = qv.x * rq * wq.x, q1 = qv.y * rq * wq.y, q2 = qv.z * rq * wq.z, q3 = qv.w * rq * wq.w;
    float k0 = kv.x * rk * wk.x, k1 = kv.y * rk * wk.y, k2 = kv.z * rk * wk.z, k3 = kv.w * rk * wk.w;

    // pe layout: (L, 64, 2, 2) -> offset l*256 + i*4 + j*2 + c; lane owns pairs i0=lane*2, i0+1
    const float* pep = pe + (size_t)l * 256 + lane * 8;
    float4 p0 = *reinterpret_cast<const float4*>(pep);
    float4 p1 = *reinterpret_cast<const float4*>(pep + 4);
    float4 qo, ko;
    qo.x = p0.x * q0 + p0.y * q1;  qo.y = p0.z * q0 + p0.w * q1;
    qo.z = p1.x * q2 + p1.y * q3;  qo.w = p1.z * q2 + p1.w * q3;
    ko.x = p0.x * k0 + p0.y * k1;  ko.y = p0.z * k0 + p0.w * k1;
    ko.z = p1.x * k2 + p1.y * k3;  ko.w = p1.z * k2 + p1.w * k3;

    size_t o = ((size_t)hd * SEQ + l) * HD + lane * 4;
    *reinterpret_cast<float4*>(d_q + o) = qo;
    *reinterpret_cast<float4*>(d_k + o) = ko;
    *reinterpret_cast<float4*>(d_v + o) = vv;
}

// ---------------- row softmax over d_s ( NH*SEQ rows of SEQ ) ---------------
__global__ void softmax_kernel() {
    float* row = d_s + (size_t)blockIdx.x * SEQ;
    int tid = threadIdx.x;
    float v[8];
    float m = -1e30f;
#pragma unroll
    for (int j = 0; j < 8; j++) { v[j] = row[tid + j * 256]; m = fmaxf(m, v[j]); }
    __shared__ float red[256];
    red[tid] = m;
    __syncthreads();
    for (int o = 128; o > 0; o >>= 1) {
        if (tid < o) red[tid] = fmaxf(red[tid], red[tid + o]);
        __syncthreads();
    }
    m = red[0];
    __syncthreads();
    float s = 0.0f;
#pragma unroll
    for (int j = 0; j < 8; j++) { v[j] = __expf(v[j] - m); s += v[j]; }
    red[tid] = s;
    __syncthreads();
    for (int o = 128; o > 0; o >>= 1) {
        if (tid < o) red[tid] += red[tid + o];
        __syncthreads();
    }
    float inv = 1.0f / red[0];
#pragma unroll
    for (int j = 0; j < 8; j++) row[tid + j * 256] = v[j] * inv;
}

// ---------------- gelu(mlp half of h) -> cat[:, HIDDEN:] --------------------
__global__ void gelu_kernel() {
    size_t g = (size_t)blockIdx.x * 256 + threadIdx.x;  // total SEQ*MLPD
    size_t r = g / MLPD;
    int j = (int)(g % MLPD);
    float xv = d_h[r * W1N + 3 * HIDDEN + j];
    float t = tanhf(0.7978845608028654f * (xv + 0.044715f * xv * xv * xv));
    d_cat[r * CATN + HIDDEN + j] = 0.5f * xv * (1.0f + t);
}

// ---------------- driver ----------------------------------------------------
extern "C" void kernel_launch(void* const* d_in, const int* in_sizes, int n_in,
                              void* d_out, int out_size) {
    const float* x     = (const float*)d_in[0];
    const float* vec   = (const float*)d_in[1];
    const float* pe    = (const float*)d_in[2];
    const float* w1    = (const float*)d_in[3];
    const float* b1    = (const float*)d_in[4];
    const float* w2    = (const float*)d_in[5];
    const float* b2    = (const float*)d_in[6];
    const float* mod_w = (const float*)d_in[7];
    const float* mod_b = (const float*)d_in[8];
    const float* qnw   = (const float*)d_in[9];
    const float* knw   = (const float*)d_in[10];
    float* out = (float*)d_out;

    float *p_mod, *p_xmod, *p_h, *p_q, *p_k, *p_v, *p_s, *p_cat;
    cudaGetSymbolAddress((void**)&p_mod,  d_mod);
    cudaGetSymbolAddress((void**)&p_xmod, d_xmod);
    cudaGetSymbolAddress((void**)&p_h,    d_h);
    cudaGetSymbolAddress((void**)&p_q,    d_q);
    cudaGetSymbolAddress((void**)&p_k,    d_k);
    cudaGetSymbolAddress((void**)&p_v,    d_v);
    cudaGetSymbolAddress((void**)&p_s,    d_s);
    cudaGetSymbolAddress((void**)&p_cat,  d_cat);

    // 1) modulation vector
    mod_gemv_kernel<<<MODN / 256, 256>>>(vec, mod_w, mod_b, p_mod);
    // 2) LN + modulate
    ln_mod_kernel<<<SEQ, 256>>>(x);
    // 3) h = x_mod @ w1 + b1
    sgemm_kernel<<<dim3(W1N / BN, SEQ / BM, 1), 256>>>(
        p_xmod, HIDDEN, 0, w1, W1N, 0, 0, p_h, W1N, 0,
        HIDDEN, 1.0f, 1, b1, nullptr, nullptr);
    // 4) split qkv, rmsnorm, rope
    qkv_prep_kernel<<<SEQ * NH / 8, 256>>>(pe, qnw, knw);
    // 5) scores = (q @ k^T) * sc     (batched over heads, NT)
    sgemm_kernel<<<dim3(SEQ / BN, SEQ / BM, NH), 256>>>(
        p_q, HD, (long long)SEQ * HD, p_k, HD, (long long)SEQ * HD, 1,
        p_s, SEQ, (long long)SEQ * SEQ,
        HD, 0.08838834764831845f, 0, nullptr, nullptr, nullptr);
    // 6) softmax rows
    softmax_kernel<<<NH * SEQ, 256>>>();
    // 7) attn = probs @ v -> cat[:, :HIDDEN] (head-interleaved columns)
    sgemm_kernel<<<dim3(HD / BN, SEQ / BM, NH), 256>>>(
        p_s, SEQ, (long long)SEQ * SEQ, p_v, HD, (long long)SEQ * HD, 0,
        p_cat, CATN, HD,
        SEQ, 1.0f, 0, nullptr, nullptr, nullptr);
    // 8) gelu(mlp) -> cat[:, HIDDEN:]
    gelu_kernel<<<(SEQ * MLPD) / 256, 256>>>();
    // 9) out = x + gate * (cat @ w2 + b2)
    sgemm_kernel<<<dim3(HIDDEN / BN, SEQ / BM, 1), 256>>>(
        p_cat, CATN, 0, w2, HIDDEN, 0, 0, out, HIDDEN, 0,
        CATN, 1.0f, 2, b2, x, p_mod + 2 * HIDDEN);
}